// round 3
// baseline (speedup 1.0000x reference)
#include <cuda_runtime.h>
#include <cuda_bf16.h>
#include <math.h>

// B=32, L=1024, C=1024, E=64, TASKS=8, K=2
#define B_ 32
#define L_ 1024
#define C_ 1024
#define E_ 64
#define T_ 8
#define Y_ELEMS (B_ * L_ * C_)   // 33554432
#define GATE_BLOCKS 32
#define SCALE_BLOCKS 8192        // 4 rows each, 32768 rows total
#define TOTAL_BLOCKS (GATE_BLOCKS + SCALE_BLOCKS)

// Scratch (__device__ globals; allocation-free rule)
__device__ float d_s[B_ * L_];    // combined gate scale per (b,l)
__device__ float d_tm[B_ * L_];   // per-batch token-mask contribution
__device__ float d_pm[B_ * E_];   // masked probs rows
__device__ int   d_flag;          // gating-done counter (0 at entry & exit)
__device__ int   d_done;          // block-completion counter (0 at entry & exit)

__device__ __forceinline__ int ld_acquire_gpu(const int* p) {
    int v;
    asm volatile("ld.acquire.gpu.b32 %0, [%1];" : "=r"(v) : "l"(p) : "memory");
    return v;
}

__global__ __launch_bounds__(256) void fused_kernel(
        const float4* __restrict__ x,
        const float*  __restrict__ x2,
        const float*  __restrict__ G,
        const float*  __restrict__ W1,
        const float*  __restrict__ b1,
        const float*  __restrict__ W2,
        float* __restrict__ out) {
    const int tid = threadIdx.x;

    if (blockIdx.x < GATE_BLOCKS) {
        // ============================ GATING ============================
        __shared__ float hg[C_];
        __shared__ float partial[4 * E_];
        __shared__ float probs_sh[E_];
        __shared__ float thresh_sh;
        __shared__ int   se1, se2;
        __shared__ float sg1, sg2;

        const int b = blockIdx.x;

        // hgate: 4 elems per thread
        {
            float xr[T_];
#pragma unroll
            for (int t = 0; t < T_; t++) xr[t] = x2[b * T_ + t];
#pragma unroll
            for (int j = 0; j < 4; j++) {
                int c = tid + j * 256;
                float h = b1[c];
#pragma unroll
                for (int t = 0; t < T_; t++) h = fmaf(xr[t], W1[t * C_ + c], h);
                h = 0.5f * h * (1.0f + erff(h * 0.70710678118654752f));
                hg[c] = h;
            }
        }
        __syncthreads();

        // logits: e = tid&63, chunk = tid>>6 covers 256 c's
        {
            const int e  = tid & 63;
            const int ch = tid >> 6;        // 0..3
            const int c0 = ch * 256;
            float acc = 0.0f;
#pragma unroll 8
            for (int j = 0; j < 256; j++) {
                int c = c0 + j;
                acc = fmaf(hg[c], W2[c * (2 * E_) + e], acc);
            }
            partial[ch * E_ + e] = acc;
        }
        __syncthreads();

        if (tid < E_) {
            float acc = partial[tid] + partial[E_ + tid]
                      + partial[2 * E_ + tid] + partial[3 * E_ + tid];
            probs_sh[tid] = acc;
        }
        __syncthreads();

        // softmax + top-2 (one thread, 64 elems)
        if (tid == 0) {
            float m = -1e30f;
#pragma unroll
            for (int e = 0; e < E_; e++) m = fmaxf(m, probs_sh[e]);
            float s = 0.0f;
#pragma unroll
            for (int e = 0; e < E_; e++) {
                float p = expf(probs_sh[e] - m);
                probs_sh[e] = p;
                s += p;
            }
            float inv = 1.0f / s;
            float m1 = -1.0f, m2 = -1.0f;
            int i1 = 0, i2 = 0;
#pragma unroll
            for (int e = 0; e < E_; e++) {
                float p = probs_sh[e] * inv + 0.0001f;
                probs_sh[e] = p;
                if (p > m1)      { m2 = m1; i2 = i1; m1 = p; i1 = e; }
                else if (p > m2) { m2 = p; i2 = e; }
            }
            se1 = i1; se2 = i2; sg1 = m1; sg2 = m2;
            thresh_sh = m2;
        }
        __syncthreads();

        if (tid < E_) {
            float p = probs_sh[tid];
            d_pm[b * E_ + tid] = (p >= thresh_sh) ? p : 0.0f;
        }

        // per-(b,l) scale + token-mask contribution; 4 l's per thread
#pragma unroll
        for (int j = 0; j < 4; j++) {
            int l = tid + j * 256;
            float ga = G[((size_t)(b * E_ + se1)) * L_ + l];
            float gb = G[((size_t)(b * E_ + se2)) * L_ + l];
            d_s[b * L_ + l]  = fmaf(sg1, ga, sg2 * gb);
            d_tm[b * L_ + l] = ga + gb;
        }

        // publish
        __threadfence();
        __syncthreads();
        if (tid == 0) atomicAdd(&d_flag, 1);
    } else {
        // ============================ SCALE =============================
        const int row0 = (blockIdx.x - GATE_BLOCKS) * 4;
        const int t = tid;

        size_t i0 = (size_t)(row0 + 0) * 256 + t;
        size_t i1 = (size_t)(row0 + 1) * 256 + t;
        size_t i2 = (size_t)(row0 + 2) * 256 + t;
        size_t i3 = (size_t)(row0 + 3) * 256 + t;

        // issue streaming loads BEFORE waiting on the flag
        float4 v0 = __ldcs(&x[i0]);
        float4 v1 = __ldcs(&x[i1]);
        float4 v2 = __ldcs(&x[i2]);
        float4 v3 = __ldcs(&x[i3]);

        // wait for gating (thread 0 spins, others wait at barrier)
        if (t == 0) {
            while (ld_acquire_gpu(&d_flag) < GATE_BLOCKS) __nanosleep(64);
        }
        __syncthreads();

        float s0 = d_s[row0 + 0];
        float s1 = d_s[row0 + 1];
        float s2 = d_s[row0 + 2];
        float s3 = d_s[row0 + 3];

        v0.x *= s0; v0.y *= s0; v0.z *= s0; v0.w *= s0;
        v1.x *= s1; v1.y *= s1; v1.z *= s1; v1.w *= s1;
        v2.x *= s2; v2.y *= s2; v2.z *= s2; v2.w *= s2;
        v3.x *= s3; v3.y *= s3; v3.z *= s3; v3.w *= s3;

        __stcs(&((float4*)out)[i0], v0);
        __stcs(&((float4*)out)[i1], v1);
        __stcs(&((float4*)out)[i2], v2);
        __stcs(&((float4*)out)[i3], v3);

        // block 32: also produce the masks (post-flag, cheap)
        if (blockIdx.x == GATE_BLOCKS) {
#pragma unroll
            for (int j = 0; j < 4; j++) {
                int l = t + j * 256;
                float tm = 0.0f;
#pragma unroll
                for (int b = 0; b < B_; b++) tm += d_tm[b * L_ + l];
                out[Y_ELEMS + E_ + l] = tm;
            }
            if (t < E_) {
                float em = 0.0f;
#pragma unroll
                for (int b = 0; b < B_; b++) em += d_pm[b * E_ + t];
                out[Y_ELEMS + t] = em;
            }
        }
    }

    // -------- reset handshake state so graph replays are deterministic ----
    __syncthreads();
    if (tid == 0) {
        int old = atomicAdd(&d_done, 1);
        if (old == TOTAL_BLOCKS - 1) {
            d_flag = 0;
            d_done = 0;
        }
    }
}

extern "C" void kernel_launch(void* const* d_in, const int* in_sizes, int n_in,
                              void* d_out, int out_size) {
    const float* x  = (const float*)d_in[0];  // input_features (32,1024,1024)
    const float* x2 = (const float*)d_in[1];  // input_features2 (32,8)
    const float* G  = (const float*)d_in[2];  // G (32,64,1024)
    const float* W1 = (const float*)d_in[3];  // W1 (8,1024)
    const float* b1 = (const float*)d_in[4];  // b1 (1024,)
    const float* W2 = (const float*)d_in[5];  // W2 (1024,128)
    float* out = (float*)d_out;

    fused_kernel<<<TOTAL_BLOCKS, 256>>>((const float4*)x, x2, G, W1, b1, W2, out);
}

// round 4
// speedup vs baseline: 1.1393x; 1.1393x over previous
#include <cuda_runtime.h>
#include <cuda_bf16.h>
#include <math.h>

// B=32, L=1024, C=1024, E=64, TASKS=8, K=2
#define B_ 32
#define L_ 1024
#define C_ 1024
#define E_ 64
#define T_ 8
#define Y_ELEMS (B_ * L_ * C_)   // 33554432

// Scratch (__device__ globals; allocation-free rule)
__device__ float d_s[B_ * L_];    // combined gate scale per (b,l)
__device__ float d_tm[B_ * L_];   // per-batch token-mask contribution
__device__ float d_pm[B_ * E_];   // masked probs rows

// ---------------------------------------------------------------------------
// Kernel 1: gating. One block of 1024 threads per batch. Fully parallel
// softmax/top-2 (warp 0, shuffle reductions). Triggers PDL at entry so the
// scale kernel can start prefetching x while gating runs.
// ---------------------------------------------------------------------------
__global__ __launch_bounds__(1024) void gate_kernel(
        const float* __restrict__ x2,
        const float* __restrict__ W1,
        const float* __restrict__ b1,
        const float* __restrict__ W2,
        const float* __restrict__ G) {
    __shared__ float hg[C_];
    __shared__ float partial[16 * E_];
    __shared__ float probs_sh[E_];
    __shared__ float thresh_sh, sg1_sh, sg2_sh;
    __shared__ int   se1_sh, se2_sh;

    const int b = blockIdx.x;
    const int tid = threadIdx.x;

    // Allow the dependent scale kernel to launch and run its load-prelude.
    cudaTriggerProgrammaticLaunchCompletion();

    // --- hgate: one element per thread ---
    {
        float xr[T_];
#pragma unroll
        for (int t = 0; t < T_; t++) xr[t] = x2[b * T_ + t];
        float h = b1[tid];
#pragma unroll
        for (int t = 0; t < T_; t++) h = fmaf(xr[t], W1[t * C_ + tid], h);
        h = 0.5f * h * (1.0f + erff(h * 0.70710678118654752f));
        hg[tid] = h;
    }
    __syncthreads();

    // --- logits partials: e = tid&63, 16 chunks of 64 c's, unroll for MLP ---
    {
        const int e  = tid & 63;
        const int c0 = (tid >> 6) * 64;
        float acc = 0.0f;
#pragma unroll 16
        for (int j = 0; j < 64; j++) {
            int c = c0 + j;
            acc = fmaf(hg[c], __ldg(&W2[c * (2 * E_) + e]), acc);
        }
        partial[(tid >> 6) * E_ + e] = acc;
    }
    __syncthreads();

    if (tid < E_) {
        float acc = 0.0f;
#pragma unroll
        for (int ch = 0; ch < 16; ch++) acc += partial[ch * E_ + tid];
        probs_sh[tid] = acc;   // logits
    }
    __syncthreads();

    // --- warp 0: softmax + top-2, each lane owns experts (lane, lane+32) ---
    if (tid < 32) {
        const float la = probs_sh[tid];
        const float lb = probs_sh[tid + 32];

        // max over 64
        float m = fmaxf(la, lb);
#pragma unroll
        for (int off = 16; off > 0; off >>= 1)
            m = fmaxf(m, __shfl_xor_sync(0xffffffffu, m, off));

        // exp + sum
        float ea = expf(la - m);
        float eb = expf(lb - m);
        float s = ea + eb;
#pragma unroll
        for (int off = 16; off > 0; off >>= 1)
            s += __shfl_xor_sync(0xffffffffu, s, off);
        const float inv = 1.0f / s;

        float pa = fmaf(ea, inv, 0.0001f);
        float pb = fmaf(eb, inv, 0.0001f);
        probs_sh[tid]      = pa;
        probs_sh[tid + 32] = pb;

        // per-lane top-2, then shuffle merge
        float t1, t2; int i1, i2;
        if (pa >= pb) { t1 = pa; i1 = tid;      t2 = pb; i2 = tid + 32; }
        else          { t1 = pb; i1 = tid + 32; t2 = pa; i2 = tid; }
#pragma unroll
        for (int off = 16; off > 0; off >>= 1) {
            float o1 = __shfl_xor_sync(0xffffffffu, t1, off);
            int  oi1 = __shfl_xor_sync(0xffffffffu, i1, off);
            float o2 = __shfl_xor_sync(0xffffffffu, t2, off);
            int  oi2 = __shfl_xor_sync(0xffffffffu, i2, off);
            if (o1 > t1) {
                if (t1 > o2) { t2 = t1; i2 = i1; }
                else         { t2 = o2; i2 = oi2; }
                t1 = o1; i1 = oi1;
            } else if (o1 > t2) {
                t2 = o1; i2 = oi1;
            }
        }
        if (tid == 0) {
            se1_sh = i1; se2_sh = i2;
            sg1_sh = t1; sg2_sh = t2;
            thresh_sh = t2;
        }
    }
    __syncthreads();

    // --- masked probs row for expert_mask ---
    if (tid < E_) {
        float p = probs_sh[tid];
        d_pm[b * E_ + tid] = (p >= thresh_sh) ? p : 0.0f;
    }

    // --- per-(b,l) scale + token-mask contribution (coalesced G reads) ---
    {
        float ga = G[((size_t)(b * E_ + se1_sh)) * L_ + tid];
        float gb = G[((size_t)(b * E_ + se2_sh)) * L_ + tid];
        d_s[b * L_ + tid]  = fmaf(sg1_sh, ga, sg2_sh * gb);
        d_tm[b * L_ + tid] = ga + gb;
    }
}

// ---------------------------------------------------------------------------
// Kernel 2: y = x * s  (bandwidth-bound). 4 rows per 256-thread block.
// PDL secondary: issues streaming loads as prelude, then waits on the gate
// grid, then multiplies and stores. Block 0 also produces the two masks.
// ---------------------------------------------------------------------------
__global__ __launch_bounds__(256) void scale_kernel(
        const float4* __restrict__ x,
        float4* __restrict__ y,
        float* __restrict__ out) {
    const int row0 = blockIdx.x * 4;
    const int t = threadIdx.x;

    const size_t i0 = (size_t)(row0 + 0) * 256 + t;
    const size_t i1 = (size_t)(row0 + 1) * 256 + t;
    const size_t i2 = (size_t)(row0 + 2) * 256 + t;
    const size_t i3 = (size_t)(row0 + 3) * 256 + t;

    // Prelude: issue streaming loads before depending on gate output.
    float4 v0 = __ldcs(&x[i0]);
    float4 v1 = __ldcs(&x[i1]);
    float4 v2 = __ldcs(&x[i2]);
    float4 v3 = __ldcs(&x[i3]);

    // Wait for the gate grid to complete.
    cudaGridDependencySynchronize();

    const float s0 = d_s[row0 + 0];
    const float s1 = d_s[row0 + 1];
    const float s2 = d_s[row0 + 2];
    const float s3 = d_s[row0 + 3];

    v0.x *= s0; v0.y *= s0; v0.z *= s0; v0.w *= s0;
    v1.x *= s1; v1.y *= s1; v1.z *= s1; v1.w *= s1;
    v2.x *= s2; v2.y *= s2; v2.z *= s2; v2.w *= s2;
    v3.x *= s3; v3.y *= s3; v3.z *= s3; v3.w *= s3;

    __stcs(&y[i0], v0);
    __stcs(&y[i1], v1);
    __stcs(&y[i2], v2);
    __stcs(&y[i3], v3);

    // Block 0: masks (output layout: [y (32M), expert_mask (64), token_mask (1024)])
    if (blockIdx.x == 0) {
#pragma unroll
        for (int j = 0; j < 4; j++) {
            int l = t + j * 256;
            float tm = 0.0f;
#pragma unroll
            for (int b = 0; b < B_; b++) tm += d_tm[b * L_ + l];
            out[Y_ELEMS + E_ + l] = tm;
        }
        if (t < E_) {
            float em = 0.0f;
#pragma unroll
            for (int b = 0; b < B_; b++) em += d_pm[b * E_ + t];
            out[Y_ELEMS + t] = em;
        }
    }
}

// ---------------------------------------------------------------------------
extern "C" void kernel_launch(void* const* d_in, const int* in_sizes, int n_in,
                              void* d_out, int out_size) {
    const float* x  = (const float*)d_in[0];  // input_features (32,1024,1024)
    const float* x2 = (const float*)d_in[1];  // input_features2 (32,8)
    const float* G  = (const float*)d_in[2];  // G (32,64,1024)
    const float* W1 = (const float*)d_in[3];  // W1 (8,1024)
    const float* b1 = (const float*)d_in[4];  // b1 (1024,)
    const float* W2 = (const float*)d_in[5];  // W2 (1024,128)
    float* out = (float*)d_out;

    gate_kernel<<<B_, 1024>>>(x2, W1, b1, W2, G);

    // PDL launch of the scale kernel: may start (prelude) while gate runs.
    cudaLaunchConfig_t cfg = {};
    cfg.gridDim  = dim3((B_ * L_) / 4, 1, 1);
    cfg.blockDim = dim3(256, 1, 1);
    cfg.dynamicSmemBytes = 0;
    cfg.stream = 0;
    cudaLaunchAttribute attrs[1];
    attrs[0].id = cudaLaunchAttributeProgrammaticStreamSerialization;
    attrs[0].val.programmaticStreamSerializationAllowed = 1;
    cfg.attrs = attrs;
    cfg.numAttrs = 1;
    cudaLaunchKernelEx(&cfg, scale_kernel, (const float4*)x, (float4*)out, out);
}